// round 2
// baseline (speedup 1.0000x reference)
#include <cuda_runtime.h>
#include <cuda_bf16.h>
#include <math.h>

// StyleLoss: x, target [B=8, C=256, H=128, W=128] fp32.
// loss = sum_{k=1..5} sqrt( sum_c (mu_k_x[c] - mu_k_t[c])^2 )
// Single pass: raw power sums S1..S5 per channel (packed f32x2 FFMA2 math),
// binomial conversion to central moments in a fused last-block finalize.

#define B_DIM 8
#define C_DIM 256
#define HW_DIM (128 * 128)          // 16384 contiguous floats per (b,c) slice
#define N_PER_CH (B_DIM * HW_DIM)   // 131072 elements reduced per channel
#define N_CTA (B_DIM * C_DIM)       // 2048 blocks, one per (b,c) slice

// Per-CTA partial sums: [cta][10] = {S1..S5 of x, S1..S5 of target}.
__device__ float g_part[N_CTA * 10];
__device__ unsigned int g_count;    // zero-init at load; last block resets to 0

typedef unsigned long long u64;

#define MUL2(d, a, b) \
    asm("mul.rn.f32x2 %0, %1, %2;" : "=l"(d) : "l"(a), "l"(b))
#define ADD2(d, a, b) \
    asm("add.rn.f32x2 %0, %1, %2;" : "=l"(d) : "l"(a), "l"(b))
#define FMA2(d, a, b, c) \
    asm("fma.rn.f32x2 %0, %1, %2, %3;" : "=l"(d) : "l"(a), "l"(b), "l"(c))
#define UNPACK2(lo, hi, p) \
    asm("mov.b64 {%0, %1}, %2;" : "=f"(lo), "=f"(hi) : "l"(p))

// 5 power sums of a packed pair: 7 f32x2 ops for 2 elements.
__device__ __forceinline__ void acc5p(u64 v, u64* s) {
    u64 v2, v3;
    MUL2(v2, v, v);
    ADD2(s[0], s[0], v);
    FMA2(s[1], v, v, s[1]);
    FMA2(s[2], v2, v, s[2]);
    FMA2(s[3], v2, v2, s[3]);
    MUL2(v3, v2, v);
    FMA2(s[4], v3, v2, s[4]);
}

__global__ __launch_bounds__(256) void style_fused(const float* __restrict__ x,
                                                   const float* __restrict__ t,
                                                   float* __restrict__ out) {
    const int cta = blockIdx.x;  // cta = b*C + c -> contiguous HW slice
    const ulonglong2* __restrict__ xp =
        reinterpret_cast<const ulonglong2*>(x) + (size_t)cta * (HW_DIM / 4);
    const ulonglong2* __restrict__ tp =
        reinterpret_cast<const ulonglong2*>(t) + (size_t)cta * (HW_DIM / 4);

    u64 sp[10];
#pragma unroll
    for (int j = 0; j < 10; j++) sp[j] = 0ull;

    // 16 x 16B iterations per thread per tensor; fully coalesced LDG.128.
#pragma unroll 4
    for (int i = threadIdx.x; i < HW_DIM / 4; i += 256) {
        ulonglong2 v = xp[i];
        ulonglong2 w = tp[i];
        acc5p(v.x, sp); acc5p(v.y, sp);
        acc5p(w.x, sp + 5); acc5p(w.y, sp + 5);
    }

    // Unpack pairs, then warp tree-reduce the 10 scalar accumulators.
    float s[10];
#pragma unroll
    for (int j = 0; j < 10; j++) {
        float lo, hi;
        UNPACK2(lo, hi, sp[j]);
        s[j] = lo + hi;
    }
#pragma unroll
    for (int j = 0; j < 10; j++) {
#pragma unroll
        for (int o = 16; o > 0; o >>= 1)
            s[j] += __shfl_down_sync(0xffffffffu, s[j], o);
    }

    __shared__ float wred[8][10];
    const int lane = threadIdx.x & 31;
    const int wid  = threadIdx.x >> 5;
    if (lane == 0) {
#pragma unroll
        for (int j = 0; j < 10; j++) wred[wid][j] = s[j];
    }
    __syncthreads();

    if (threadIdx.x < 10) {
        float v = 0.0f;
#pragma unroll
        for (int w = 0; w < 8; w++) v += wred[w][threadIdx.x];
        g_part[cta * 10 + threadIdx.x] = v;
    }

    // ---- last-block fused finalize ----
    __shared__ int is_last;
    if (threadIdx.x == 0) {
        __threadfence();  // publish g_part before counting
        unsigned int prev = atomicAdd(&g_count, 1u);
        is_last = (prev == (unsigned int)(N_CTA - 1)) ? 1 : 0;
    }
    __syncthreads();
    if (!is_last) return;

    if (threadIdx.x == 0) g_count = 0;  // reset for next graph replay
    __threadfence();                     // acquire: see all g_part writes

    const int c = threadIdx.x;  // one thread per channel
    float f[10];
#pragma unroll
    for (int j = 0; j < 10; j++) f[j] = 0.0f;
#pragma unroll
    for (int b = 0; b < B_DIM; b++) {
        const float* p = g_part + (size_t)(b * C_DIM + c) * 10;
#pragma unroll
        for (int j = 0; j < 10; j++) f[j] += p[j];
    }

    const float invN = 1.0f / (float)N_PER_CH;
    float d[5];
    {
        float m  = f[0] * invN, M2 = f[1] * invN, M3 = f[2] * invN,
              M4 = f[3] * invN, M5 = f[4] * invN;
        float n  = f[5] * invN, T2 = f[6] * invN, T3 = f[7] * invN,
              T4 = f[8] * invN, T5 = f[9] * invN;

        float m2 = m * m, m3 = m2 * m;
        float mu2x = M2 - m2;
        float mu3x = M3 - 3.0f * m * M2 + 2.0f * m3;
        float mu4x = M4 - 4.0f * m * M3 + 6.0f * m2 * M2 - 3.0f * m2 * m2;
        float mu5x = M5 - 5.0f * m * M4 + 10.0f * m2 * M3 - 10.0f * m3 * M2
                     + 4.0f * m3 * m2;

        float n2 = n * n, n3 = n2 * n;
        float mu2t = T2 - n2;
        float mu3t = T3 - 3.0f * n * T2 + 2.0f * n3;
        float mu4t = T4 - 4.0f * n * T3 + 6.0f * n2 * T2 - 3.0f * n2 * n2;
        float mu5t = T5 - 5.0f * n * T4 + 10.0f * n2 * T3 - 10.0f * n3 * T2
                     + 4.0f * n3 * n2;

        d[0] = m - n;
        d[1] = mu2x - mu2t;
        d[2] = mu3x - mu3t;
        d[3] = mu4x - mu4t;
        d[4] = mu5x - mu5t;
    }

    __shared__ float fred[5][C_DIM];
#pragma unroll
    for (int i = 0; i < 5; i++) fred[i][c] = d[i] * d[i];
    __syncthreads();

    for (int off = 128; off > 0; off >>= 1) {
        if (c < off) {
#pragma unroll
            for (int i = 0; i < 5; i++) fred[i][c] += fred[i][c + off];
        }
        __syncthreads();
    }

    if (c == 0) {
        out[0] = sqrtf(fred[0][0]) + sqrtf(fred[1][0]) + sqrtf(fred[2][0]) +
                 sqrtf(fred[3][0]) + sqrtf(fred[4][0]);
    }
}

extern "C" void kernel_launch(void* const* d_in, const int* in_sizes, int n_in,
                              void* d_out, int out_size) {
    const float* x = (const float*)d_in[0];
    const float* t = (const float*)d_in[1];
    float* out = (float*)d_out;
    style_fused<<<N_CTA, 256>>>(x, t, out);
}